// round 4
// baseline (speedup 1.0000x reference)
#include <cuda_runtime.h>
#include <math.h>
#include <stdint.h>

// Problem constants
#define BATCH   8
#define SEQ     2048
#define HID     1024
#define NPB     (SEQ * HID)        // 2,097,152 elements per batch
#define VEC_PB  (NPB / 4)          // 524,288 float4 per batch
#define TOTALV  (BATCH * VEC_PB)   // 4,194,304 float4 total
#define RANK0   1048576u           // 0-indexed ascending rank of threshold (N - k)
#define SEGS    128                // compact blocks per batch
#define SEG_CAP 16384              // worst case: every value in a block matches

// Static scratch (no runtime allocation allowed)
__device__ __align__(16) float    g_imp5[5 * HID];            // sigmoid(band)*sigmoid(dim)
__device__ unsigned               g_hist[3][BATCH][2048];
__device__ unsigned               g_blk_cnt[BATCH][SEGS];
__device__ unsigned               g_cand[BATCH][SEGS][SEG_CAP]; // 64 MB candidate buffer
__device__ float                  g_thr[BATCH];

__device__ __forceinline__ float sigmoidf_fast(float x) {
    return 1.0f / (1.0f + __expf(-x));
}

// band(t): 0 for t<128, else floor(log2(t>>7)) + 1   (T=2048, L=4)
__device__ __forceinline__ int band_of(int t) {
    return (t >= 128) ? (32 - __clz(t >> 7)) : 0;
}

// ---------------------------------------------------------------------------
// setup: zero histograms + per-segment counts, build importance table
// ---------------------------------------------------------------------------
__global__ void setup_kernel(const float* __restrict__ bi, const float* __restrict__ di) {
    int i = blockIdx.x * blockDim.x + threadIdx.x;
    if (i < 3 * BATCH * 2048) ((unsigned*)g_hist)[i] = 0;
    if (i < BATCH * SEGS)     ((unsigned*)g_blk_cnt)[i] = 0;
    if (i < 5 * HID) {
        float sb = sigmoidf_fast(bi[i]);
        float sd = sigmoidf_fast(di[i & (HID - 1)]);
        g_imp5[i] = sb * sd;
    }
}

// 4 consecutive importance-weighted |coeffs| for vec index within a batch
__device__ __forceinline__ float4 compute_ci4(const float4* __restrict__ cb, int ve_in_batch) {
    int eb = ve_in_batch << 2;
    int t = eb >> 10;
    int d = eb & (HID - 1);
    int band = band_of(t);
    float4 imp = *reinterpret_cast<const float4*>(&g_imp5[band * HID + d]);
    float4 c = __ldg(&cb[ve_in_batch]);
    float4 r;
    r.x = imp.x * fabsf(c.x);
    r.y = imp.y * fabsf(c.y);
    r.z = imp.z * fabsf(c.z);
    r.w = imp.w * fabsf(c.w);
    return r;
}

// warp-collective digit select over a 32*PER-bin histogram.
// All 32 lanes return the digit; *rem gets the rank remaining within it.
template <int PER>
__device__ __forceinline__ unsigned warp_select(const unsigned* __restrict__ h,
                                                unsigned rank, unsigned* rem) {
    const int lane = threadIdx.x & 31;
    unsigned s = 0;
    #pragma unroll
    for (int j = 0; j < PER; j++) s += h[lane * PER + j];

    unsigned v = s;
    #pragma unroll
    for (int o = 1; o < 32; o <<= 1) {
        unsigned t = __shfl_up_sync(0xFFFFFFFFu, v, o);
        if (lane >= o) v += t;
    }
    unsigned excl = v - s;

    bool in = (rank >= excl) && (rank < excl + s);
    unsigned m = __ballot_sync(0xFFFFFFFFu, in);
    int L = __ffs(m) - 1;

    unsigned dig = 0, r2 = 0;
    if (lane == L) {
        unsigned cum = excl;
        #pragma unroll 1
        for (int j = 0; j < PER; j++) {
            unsigned c = h[lane * PER + j];
            if (rank < cum + c) { dig = (unsigned)(lane * PER + j); r2 = rank - cum; break; }
            cum += c;
        }
    }
    dig = __shfl_sync(0xFFFFFFFFu, dig, L);
    r2  = __shfl_sync(0xFFFFFFFFu, r2,  L);
    *rem = r2;
    return dig;
}

#define LOAD16(bb, cb, base, i)                                            \
    {                                                                      \
        float4 v0 = compute_ci4(cb, (base) + (i));                         \
        float4 v1 = compute_ci4(cb, (base) + (i) + 256);                   \
        float4 v2 = compute_ci4(cb, (base) + (i) + 512);                   \
        float4 v3 = compute_ci4(cb, (base) + (i) + 768);                   \
        bb[0]  = __float_as_uint(v0.x); bb[1]  = __float_as_uint(v0.y);    \
        bb[2]  = __float_as_uint(v0.z); bb[3]  = __float_as_uint(v0.w);    \
        bb[4]  = __float_as_uint(v1.x); bb[5]  = __float_as_uint(v1.y);    \
        bb[6]  = __float_as_uint(v1.z); bb[7]  = __float_as_uint(v1.w);    \
        bb[8]  = __float_as_uint(v2.x); bb[9]  = __float_as_uint(v2.y);    \
        bb[10] = __float_as_uint(v2.z); bb[11] = __float_as_uint(v2.w);    \
        bb[12] = __float_as_uint(v3.x); bb[13] = __float_as_uint(v3.y);    \
        bb[14] = __float_as_uint(v3.z); bb[15] = __float_as_uint(v3.w);    \
    }

// ---------------------------------------------------------------------------
// pass 0: histogram bits[31:21]. grid (SEGS, BATCH) x 256.
// match_any aggregation collapses duplicate digits within a warp.
// ---------------------------------------------------------------------------
__global__ void __launch_bounds__(256) hist0_kernel(const float4* __restrict__ coeffs) {
    __shared__ unsigned sh[4][2048];
    const int tid  = threadIdx.x;
    const int warp = tid >> 5;
    const int lane = tid & 31;

    for (int i = tid; i < 4 * 2048; i += 256) ((unsigned*)sh)[i] = 0;
    __syncthreads();

    const int batch = blockIdx.y;
    unsigned* h = sh[warp & 3];
    const int base = blockIdx.x * (VEC_PB / SEGS);   // 4096 float4 per block
    const float4* cb = coeffs + (size_t)batch * VEC_PB;

    for (int i = tid; i < VEC_PB / SEGS; i += 1024) {
        unsigned bb[16];
        LOAD16(bb, cb, base, i);
        #pragma unroll
        for (int j = 0; j < 16; j++) {
            unsigned dig = bb[j] >> 21;
            unsigned peers = __match_any_sync(0xFFFFFFFFu, dig);
            if (lane == __ffs(peers) - 1) atomicAdd(&h[dig], __popc(peers));
        }
    }
    __syncthreads();

    for (int i = tid; i < 2048; i += 256) {
        unsigned s = sh[0][i] + sh[1][i] + sh[2][i] + sh[3][i];
        if (s) atomicAdd(&g_hist[0][batch][i], s);
    }
}

// ---------------------------------------------------------------------------
// pass 1 (fused select-0 + compaction): values matching prefix bits[31:21]
// are histogrammed on bits[20:10] AND appended to this block's segment.
// grid (SEGS, BATCH) x 256.
// ---------------------------------------------------------------------------
__global__ void __launch_bounds__(256) compact_kernel(const float4* __restrict__ coeffs) {
    __shared__ unsigned sh[2][2048];
    __shared__ unsigned s_cnt;
    __shared__ unsigned s_d0;
    const int tid  = threadIdx.x;
    const int warp = tid >> 5;
    const int lane = tid & 31;

    for (int i = tid; i < 2 * 2048; i += 256) ((unsigned*)sh)[i] = 0;
    if (tid == 0) s_cnt = 0;
    __syncthreads();

    const int batch = blockIdx.y;
    if (warp == 0) {
        unsigned r1;
        unsigned d0 = warp_select<64>(g_hist[0][batch], RANK0, &r1);
        if (lane == 0) s_d0 = d0;
    }
    __syncthreads();

    const unsigned pref21 = s_d0;
    unsigned* h   = sh[warp & 1];
    unsigned* seg = g_cand[batch][blockIdx.x];
    const int base = blockIdx.x * (VEC_PB / SEGS);
    const float4* cb = coeffs + (size_t)batch * VEC_PB;

    for (int i = tid; i < VEC_PB / SEGS; i += 1024) {
        unsigned bb[16];
        LOAD16(bb, cb, base, i);
        #pragma unroll
        for (int j = 0; j < 16; j++) {
            unsigned b = bb[j];
            bool ok = (b >> 21) == pref21;
            unsigned m = __ballot_sync(0xFFFFFFFFu, ok);
            if (m) {
                int ldr = __ffs(m) - 1;
                unsigned bs = 0;
                if (lane == ldr) bs = atomicAdd(&s_cnt, __popc(m));
                bs = __shfl_sync(0xFFFFFFFFu, bs, ldr);
                if (ok) {
                    seg[bs + __popc(m & ((1u << lane) - 1))] = b;
                    atomicAdd(&h[(b >> 10) & 2047], 1u);
                }
            }
        }
    }
    __syncthreads();

    for (int i = tid; i < 2048; i += 256) {
        unsigned s = sh[0][i] + sh[1][i];
        if (s) atomicAdd(&g_hist[1][batch][i], s);
    }
    if (tid == 0) g_blk_cnt[batch][blockIdx.x] = s_cnt;
}

// ---------------------------------------------------------------------------
// pass 2 (fused selects 0,1): over candidates only (~5% of data).
// grid (SEGS, BATCH) x 256 — one block per segment.
// ---------------------------------------------------------------------------
__global__ void __launch_bounds__(256) candhist_kernel() {
    __shared__ unsigned sh[1024];
    __shared__ unsigned s_pref;   // bits[31:10] of threshold prefix
    const int tid  = threadIdx.x;
    const int warp = tid >> 5;
    const int lane = tid & 31;

    for (int i = tid; i < 1024; i += 256) sh[i] = 0;

    const int batch = blockIdx.y;
    if (warp == 0) {
        unsigned r1, r2;
        unsigned d0 = warp_select<64>(g_hist[0][batch], RANK0, &r1);
        unsigned d1 = warp_select<64>(g_hist[1][batch], r1, &r2);
        if (lane == 0) s_pref = (d0 << 11) | d1;
    }
    __syncthreads();

    const unsigned pref = s_pref;
    const unsigned n = g_blk_cnt[batch][blockIdx.x];
    const unsigned* __restrict__ seg = g_cand[batch][blockIdx.x];

    for (unsigned i = tid; i < n; i += 256) {
        unsigned b = seg[i];
        if ((b >> 10) == pref) atomicAdd(&sh[b & 1023], 1u);
    }
    __syncthreads();

    for (int i = tid; i < 1024; i += 256)
        if (sh[i]) atomicAdd(&g_hist[2][batch][i], sh[i]);
}

// ---------------------------------------------------------------------------
// final select: reconstruct exact threshold bit pattern per batch
// ---------------------------------------------------------------------------
__global__ void select_final_kernel() {
    const int b = blockIdx.x;
    unsigned r1, r2, r3;
    unsigned d0 = warp_select<64>(g_hist[0][b], RANK0, &r1);
    unsigned d1 = warp_select<64>(g_hist[1][b], r1, &r2);
    unsigned d2 = warp_select<32>(g_hist[2][b], r2, &r3);
    if (threadIdx.x == 0)
        g_thr[b] = __uint_as_float((d0 << 21) | (d1 << 10) | d2);
}

// ---------------------------------------------------------------------------
// final: out[0..V)=coeffs*mask, out[V..2V)=mask, out[2V..3V)=importance
// ---------------------------------------------------------------------------
__global__ void __launch_bounds__(256) final_kernel(const float4* __restrict__ coeffs,
                                                    const float* __restrict__ temp,
                                                    float4* __restrict__ out) {
    int ve = blockIdx.x * blockDim.x + threadIdx.x;   // 0 .. TOTALV-1
    int batch = ve >> 19;                             // VEC_PB = 2^19
    int vein = ve & (VEC_PB - 1);
    int eb = vein << 2;
    int t = eb >> 10;
    int d = eb & (HID - 1);
    int band = band_of(t);

    float4 imp = *reinterpret_cast<const float4*>(&g_imp5[band * HID + d]);
    float4 c = __ldg(&coeffs[ve]);
    float thr = g_thr[batch];
    float inv_t = __frcp_rn(fabsf(__ldg(&temp[0])));

    float4 mk, fl;
    { float ci = imp.x * fabsf(c.x); mk.x = sigmoidf_fast((ci - thr) * inv_t); fl.x = c.x * mk.x; }
    { float ci = imp.y * fabsf(c.y); mk.y = sigmoidf_fast((ci - thr) * inv_t); fl.y = c.y * mk.y; }
    { float ci = imp.z * fabsf(c.z); mk.z = sigmoidf_fast((ci - thr) * inv_t); fl.z = c.z * mk.z; }
    { float ci = imp.w * fabsf(c.w); mk.w = sigmoidf_fast((ci - thr) * inv_t); fl.w = c.w * mk.w; }

    out[ve] = fl;
    out[TOTALV + ve] = mk;
    out[2 * TOTALV + ve] = imp;
}

// ---------------------------------------------------------------------------
// launch
// ---------------------------------------------------------------------------
extern "C" void kernel_launch(void* const* d_in, const int* in_sizes, int n_in,
                              void* d_out, int out_size) {
    const float* coeffs = (const float*)d_in[0];
    const float* bi     = (const float*)d_in[1];
    const float* di     = (const float*)d_in[2];
    const float* temp   = (const float*)d_in[3];
    float* out = (float*)d_out;

    setup_kernel<<<(3 * BATCH * 2048 + 255) / 256, 256>>>(bi, di);

    dim3 g(SEGS, BATCH);
    hist0_kernel<<<g, 256>>>((const float4*)coeffs);
    compact_kernel<<<g, 256>>>((const float4*)coeffs);
    candhist_kernel<<<g, 256>>>();
    select_final_kernel<<<BATCH, 32>>>();

    final_kernel<<<TOTALV / 256, 256>>>((const float4*)coeffs, temp, (float4*)out);
}

// round 5
// speedup vs baseline: 1.2951x; 1.2951x over previous
#include <cuda_runtime.h>
#include <math.h>
#include <stdint.h>

// Problem constants
#define BATCH   8
#define SEQ     2048
#define HID     1024
#define NPB     (SEQ * HID)        // 2,097,152 elements per batch
#define VEC_PB  (NPB / 4)          // 524,288 float4 per batch
#define TOTALV  (BATCH * VEC_PB)   // 4,194,304 float4 total
#define RANK0   1048576u           // 0-indexed ascending rank of threshold (N - k)
#define HBLK    128                // hist blocks per batch

// Static scratch (no runtime allocation allowed)
__device__ __align__(16) float    g_imp5[5 * HID];       // sigmoid(band)*sigmoid(dim)
__device__ unsigned               g_hist[2][BATCH][2048];
__device__ unsigned               g_d0[BATCH];           // selected digit, pass 0
__device__ unsigned               g_r1[BATCH];           // remaining rank after pass 0
__device__ float                  g_thr[BATCH];

__device__ __forceinline__ float sigmoidf_fast(float x) {
    return 1.0f / (1.0f + __expf(-x));
}

// band(t): 0 for t<128, else floor(log2(t>>7)) + 1   (T=2048, L=4)
__device__ __forceinline__ int band_of(int t) {
    return (t >= 128) ? (32 - __clz(t >> 7)) : 0;
}

// ---------------------------------------------------------------------------
// setup: zero histograms, build importance table
// ---------------------------------------------------------------------------
__global__ void setup_kernel(const float* __restrict__ bi, const float* __restrict__ di) {
    int i = blockIdx.x * blockDim.x + threadIdx.x;
    if (i < 2 * BATCH * 2048) ((unsigned*)g_hist)[i] = 0;
    if (i < 5 * HID) {
        float sb = sigmoidf_fast(bi[i]);
        float sd = sigmoidf_fast(di[i & (HID - 1)]);
        g_imp5[i] = sb * sd;
    }
}

// 4 consecutive importance-weighted |coeffs| for vec index within a batch
__device__ __forceinline__ float4 compute_ci4(const float4* __restrict__ cb, int ve_in_batch) {
    int eb = ve_in_batch << 2;
    int t = eb >> 10;
    int d = eb & (HID - 1);
    int band = band_of(t);
    float4 imp = *reinterpret_cast<const float4*>(&g_imp5[band * HID + d]);
    float4 c = __ldg(&cb[ve_in_batch]);
    float4 r;
    r.x = imp.x * fabsf(c.x);
    r.y = imp.y * fabsf(c.y);
    r.z = imp.z * fabsf(c.z);
    r.w = imp.w * fabsf(c.w);
    return r;
}

#define LOAD16(bb, cb, base, i)                                            \
    {                                                                      \
        float4 v0 = compute_ci4(cb, (base) + (i));                         \
        float4 v1 = compute_ci4(cb, (base) + (i) + 256);                   \
        float4 v2 = compute_ci4(cb, (base) + (i) + 512);                   \
        float4 v3 = compute_ci4(cb, (base) + (i) + 768);                   \
        bb[0]  = __float_as_uint(v0.x); bb[1]  = __float_as_uint(v0.y);    \
        bb[2]  = __float_as_uint(v0.z); bb[3]  = __float_as_uint(v0.w);    \
        bb[4]  = __float_as_uint(v1.x); bb[5]  = __float_as_uint(v1.y);    \
        bb[6]  = __float_as_uint(v1.z); bb[7]  = __float_as_uint(v1.w);    \
        bb[8]  = __float_as_uint(v2.x); bb[9]  = __float_as_uint(v2.y);    \
        bb[10] = __float_as_uint(v2.z); bb[11] = __float_as_uint(v2.w);    \
        bb[12] = __float_as_uint(v3.x); bb[13] = __float_as_uint(v3.y);    \
        bb[14] = __float_as_uint(v3.z); bb[15] = __float_as_uint(v3.w);    \
    }

// ---------------------------------------------------------------------------
// pass 0: histogram bits[31:21]. grid (HBLK, BATCH) x 256.
// 4-replica shared hist + warp-aggregated atomics (hot exponent bins).
// ---------------------------------------------------------------------------
__global__ void __launch_bounds__(256) hist0_kernel(const float4* __restrict__ coeffs) {
    __shared__ unsigned sh[4][2048];
    const int tid  = threadIdx.x;
    const int warp = tid >> 5;
    const int lane = tid & 31;

    for (int i = tid; i < 4 * 2048; i += 256) ((unsigned*)sh)[i] = 0;
    __syncthreads();

    const int batch = blockIdx.y;
    unsigned* h = sh[warp & 3];
    const int base = blockIdx.x * (VEC_PB / HBLK);   // 4096 float4 per block
    const float4* cb = coeffs + (size_t)batch * VEC_PB;

    for (int i = tid; i < VEC_PB / HBLK; i += 1024) {
        unsigned bb[16];
        LOAD16(bb, cb, base, i);
        #pragma unroll
        for (int j = 0; j < 16; j++) {
            unsigned dig = bb[j] >> 21;
            unsigned peers = __match_any_sync(0xFFFFFFFFu, dig);
            if (lane == __ffs(peers) - 1) atomicAdd(&h[dig], __popc(peers));
        }
    }
    __syncthreads();

    for (int i = tid; i < 2048; i += 256) {
        unsigned s = sh[0][i] + sh[1][i] + sh[2][i] + sh[3][i];
        if (s) atomicAdd(&g_hist[0][batch][i], s);
    }
}

// ---------------------------------------------------------------------------
// warp-collective digit select over a 32*PER-bin histogram.
// All 32 lanes return the digit; *rem gets the remaining rank within it.
// ---------------------------------------------------------------------------
template <int PER>
__device__ __forceinline__ unsigned warp_select(const unsigned* __restrict__ h,
                                                unsigned rank, unsigned* rem) {
    const int lane = threadIdx.x & 31;
    unsigned s = 0;
    #pragma unroll
    for (int j = 0; j < PER; j++) s += h[lane * PER + j];

    unsigned v = s;
    #pragma unroll
    for (int o = 1; o < 32; o <<= 1) {
        unsigned t = __shfl_up_sync(0xFFFFFFFFu, v, o);
        if (lane >= o) v += t;
    }
    unsigned excl = v - s;

    bool in = (rank >= excl) && (rank < excl + s);
    unsigned m = __ballot_sync(0xFFFFFFFFu, in);
    int L = __ffs(m) - 1;

    unsigned dig = 0, r2 = 0;
    if (lane == L) {
        unsigned cum = excl;
        #pragma unroll 1
        for (int j = 0; j < PER; j++) {
            unsigned c = h[lane * PER + j];
            if (rank < cum + c) { dig = (unsigned)(lane * PER + j); r2 = rank - cum; break; }
            cum += c;
        }
    }
    dig = __shfl_sync(0xFFFFFFFFu, dig, L);
    r2  = __shfl_sync(0xFFFFFFFFu, r2,  L);
    *rem = r2;
    return dig;
}

// select pass 0: one block, warp w handles batch w
__global__ void select0_kernel() {
    const int b = threadIdx.x >> 5;
    if (b >= BATCH) return;
    unsigned r1;
    unsigned d0 = warp_select<64>(g_hist[0][b], RANK0, &r1);
    if ((threadIdx.x & 31) == 0) { g_d0[b] = d0; g_r1[b] = r1; }
}

// ---------------------------------------------------------------------------
// pass 1: histogram bits[20:10] among values whose bits[31:21] == d0.
// grid (HBLK, BATCH) x 256. Sparse updates (~few % match) -> single smem copy.
// ---------------------------------------------------------------------------
__global__ void __launch_bounds__(256) hist1_kernel(const float4* __restrict__ coeffs) {
    __shared__ unsigned sh[2][2048];
    const int tid  = threadIdx.x;
    const int warp = tid >> 5;

    for (int i = tid; i < 2 * 2048; i += 256) ((unsigned*)sh)[i] = 0;
    __syncthreads();

    const int batch = blockIdx.y;
    const unsigned pref = g_d0[batch];
    unsigned* h = sh[warp & 1];
    const int base = blockIdx.x * (VEC_PB / HBLK);
    const float4* cb = coeffs + (size_t)batch * VEC_PB;

    for (int i = tid; i < VEC_PB / HBLK; i += 1024) {
        unsigned bb[16];
        LOAD16(bb, cb, base, i);
        #pragma unroll
        for (int j = 0; j < 16; j++) {
            unsigned b = bb[j];
            if ((b >> 21) == pref) atomicAdd(&h[(b >> 10) & 2047], 1u);
        }
    }
    __syncthreads();

    for (int i = tid; i < 2048; i += 256) {
        unsigned s = sh[0][i] + sh[1][i];
        if (s) atomicAdd(&g_hist[1][batch][i], s);
    }
}

// select pass 1: threshold = midpoint of resolved 1024-ulp bin
// (relative error <= 2^-14; mask relative error <= ~3e-5, tolerance 1e-3)
__global__ void select1_kernel() {
    const int b = threadIdx.x >> 5;
    if (b >= BATCH) return;
    unsigned r2;
    unsigned d1 = warp_select<64>(g_hist[1][b], g_r1[b], &r2);
    if ((threadIdx.x & 31) == 0)
        g_thr[b] = __uint_as_float((g_d0[b] << 21) | (d1 << 10) | 512u);
}

// ---------------------------------------------------------------------------
// final: out[0..V)=coeffs*mask, out[V..2V)=mask, out[2V..3V)=importance
// ---------------------------------------------------------------------------
__global__ void __launch_bounds__(256) final_kernel(const float4* __restrict__ coeffs,
                                                    const float* __restrict__ temp,
                                                    float4* __restrict__ out) {
    int ve = blockIdx.x * blockDim.x + threadIdx.x;   // 0 .. TOTALV-1
    int batch = ve >> 19;                             // VEC_PB = 2^19
    int vein = ve & (VEC_PB - 1);
    int eb = vein << 2;
    int t = eb >> 10;
    int d = eb & (HID - 1);
    int band = band_of(t);

    float4 imp = *reinterpret_cast<const float4*>(&g_imp5[band * HID + d]);
    float4 c = __ldg(&coeffs[ve]);
    float thr = g_thr[batch];
    float inv_t = __frcp_rn(fabsf(__ldg(&temp[0])));

    float4 mk, fl;
    { float ci = imp.x * fabsf(c.x); mk.x = sigmoidf_fast((ci - thr) * inv_t); fl.x = c.x * mk.x; }
    { float ci = imp.y * fabsf(c.y); mk.y = sigmoidf_fast((ci - thr) * inv_t); fl.y = c.y * mk.y; }
    { float ci = imp.z * fabsf(c.z); mk.z = sigmoidf_fast((ci - thr) * inv_t); fl.z = c.z * mk.z; }
    { float ci = imp.w * fabsf(c.w); mk.w = sigmoidf_fast((ci - thr) * inv_t); fl.w = c.w * mk.w; }

    out[ve] = fl;
    out[TOTALV + ve] = mk;
    out[2 * TOTALV + ve] = imp;
}

// ---------------------------------------------------------------------------
// launch
// ---------------------------------------------------------------------------
extern "C" void kernel_launch(void* const* d_in, const int* in_sizes, int n_in,
                              void* d_out, int out_size) {
    const float* coeffs = (const float*)d_in[0];
    const float* bi     = (const float*)d_in[1];
    const float* di     = (const float*)d_in[2];
    const float* temp   = (const float*)d_in[3];
    float* out = (float*)d_out;

    setup_kernel<<<(2 * BATCH * 2048 + 255) / 256, 256>>>(bi, di);

    dim3 g(HBLK, BATCH);
    hist0_kernel<<<g, 256>>>((const float4*)coeffs);
    select0_kernel<<<1, 256>>>();
    hist1_kernel<<<g, 256>>>((const float4*)coeffs);
    select1_kernel<<<1, 256>>>();

    final_kernel<<<TOTALV / 256, 256>>>((const float4*)coeffs, temp, (float4*)out);
}

// round 6
// speedup vs baseline: 1.9262x; 1.4873x over previous
#include <cuda_runtime.h>
#include <math.h>
#include <stdint.h>

// Problem constants
#define BATCH   8
#define SEQ     2048
#define HID     1024
#define NPB     (SEQ * HID)        // 2,097,152 elements per batch
#define VEC_PB  (NPB / 4)          // 524,288 float4 per batch
#define TOTALV  (BATCH * VEC_PB)   // 4,194,304 float4 total
#define RANK0   1048576u           // 0-indexed ascending rank of threshold (N - k)
#define HBLK    128                // hist blocks per batch
#define PER_BLK (VEC_PB / HBLK)    // 4096 float4 per block

// Static scratch (no runtime allocation allowed)
__device__ __align__(16) float    g_imp5[5 * HID];       // sigmoid(band)*sigmoid(dim)
__device__ unsigned               g_hist[2][BATCH][2048];
__device__ unsigned               g_d0[BATCH];           // selected digit, pass 0
__device__ unsigned               g_r1[BATCH];           // remaining rank after pass 0
__device__ float                  g_thr[BATCH];

__device__ __forceinline__ float sigmoidf_fast(float x) {
    return 1.0f / (1.0f + __expf(-x));
}

// band(t): 0 for t<128, else floor(log2(t>>7)) + 1   (T=2048, L=4)
__device__ __forceinline__ int band_of(int t) {
    return (t >= 128) ? (32 - __clz(t >> 7)) : 0;
}

// ---------------------------------------------------------------------------
// setup: zero histograms, build importance table
// ---------------------------------------------------------------------------
__global__ void setup_kernel(const float* __restrict__ bi, const float* __restrict__ di) {
    int i = blockIdx.x * blockDim.x + threadIdx.x;
    if (i < 2 * BATCH * 2048) ((unsigned*)g_hist)[i] = 0;
    if (i < 5 * HID) {
        float sb = sigmoidf_fast(bi[i]);
        float sd = sigmoidf_fast(di[i & (HID - 1)]);
        g_imp5[i] = sb * sd;
    }
}

// 4 consecutive importance-weighted |coeffs| for vec index within a batch
__device__ __forceinline__ float4 compute_ci4(const float4* __restrict__ cb, int ve_in_batch) {
    int eb = ve_in_batch << 2;
    int t = eb >> 10;
    int d = eb & (HID - 1);
    int band = band_of(t);
    float4 imp = *reinterpret_cast<const float4*>(&g_imp5[band * HID + d]);
    float4 c = __ldg(&cb[ve_in_batch]);
    float4 r;
    r.x = imp.x * fabsf(c.x);
    r.y = imp.y * fabsf(c.y);
    r.z = imp.z * fabsf(c.z);
    r.w = imp.w * fabsf(c.w);
    return r;
}

// two independent float4 chains in flight (R2-proven register budget)
#define LOAD8(bb, cb, base, i)                                             \
    {                                                                      \
        float4 v0 = compute_ci4(cb, (base) + (i));                         \
        float4 v1 = compute_ci4(cb, (base) + (i) + 256);                   \
        bb[0] = __float_as_uint(v0.x); bb[1] = __float_as_uint(v0.y);      \
        bb[2] = __float_as_uint(v0.z); bb[3] = __float_as_uint(v0.w);      \
        bb[4] = __float_as_uint(v1.x); bb[5] = __float_as_uint(v1.y);      \
        bb[6] = __float_as_uint(v1.z); bb[7] = __float_as_uint(v1.w);      \
    }

// ---------------------------------------------------------------------------
// pass 0: histogram bits[31:21]. grid (HBLK, BATCH) x 256.
// 4-replica shared hist, plain atomics (match_any was a 3x regression).
// ---------------------------------------------------------------------------
__global__ void __launch_bounds__(256) hist0_kernel(const float4* __restrict__ coeffs) {
    __shared__ unsigned sh[4][2048];
    const int tid  = threadIdx.x;
    const int warp = tid >> 5;

    for (int i = tid; i < 4 * 2048; i += 256) ((unsigned*)sh)[i] = 0;
    __syncthreads();

    const int batch = blockIdx.y;
    unsigned* h = sh[warp & 3];
    const int base = blockIdx.x * PER_BLK;
    const float4* cb = coeffs + (size_t)batch * VEC_PB;

    for (int i = tid; i < PER_BLK; i += 512) {
        unsigned bb[8];
        LOAD8(bb, cb, base, i);
        #pragma unroll
        for (int j = 0; j < 8; j++) atomicAdd(&h[bb[j] >> 21], 1u);
    }
    __syncthreads();

    for (int i = tid; i < 2048; i += 256) {
        unsigned s = sh[0][i] + sh[1][i] + sh[2][i] + sh[3][i];
        if (s) atomicAdd(&g_hist[0][batch][i], s);
    }
}

// ---------------------------------------------------------------------------
// warp-collective digit select over a 32*PER-bin histogram.
// All 32 lanes return the digit; *rem gets the remaining rank within it.
// ---------------------------------------------------------------------------
template <int PER>
__device__ __forceinline__ unsigned warp_select(const unsigned* __restrict__ h,
                                                unsigned rank, unsigned* rem) {
    const int lane = threadIdx.x & 31;
    unsigned s = 0;
    #pragma unroll
    for (int j = 0; j < PER; j++) s += h[lane * PER + j];

    unsigned v = s;
    #pragma unroll
    for (int o = 1; o < 32; o <<= 1) {
        unsigned t = __shfl_up_sync(0xFFFFFFFFu, v, o);
        if (lane >= o) v += t;
    }
    unsigned excl = v - s;

    bool in = (rank >= excl) && (rank < excl + s);
    unsigned m = __ballot_sync(0xFFFFFFFFu, in);
    int L = __ffs(m) - 1;

    unsigned dig = 0, r2 = 0;
    if (lane == L) {
        unsigned cum = excl;
        #pragma unroll 1
        for (int j = 0; j < PER; j++) {
            unsigned c = h[lane * PER + j];
            if (rank < cum + c) { dig = (unsigned)(lane * PER + j); r2 = rank - cum; break; }
            cum += c;
        }
    }
    dig = __shfl_sync(0xFFFFFFFFu, dig, L);
    r2  = __shfl_sync(0xFFFFFFFFu, r2,  L);
    *rem = r2;
    return dig;
}

// select pass 0: one block, warp w handles batch w
__global__ void select0_kernel() {
    const int b = threadIdx.x >> 5;
    if (b >= BATCH) return;
    unsigned r1;
    unsigned d0 = warp_select<64>(g_hist[0][b], RANK0, &r1);
    if ((threadIdx.x & 31) == 0) { g_d0[b] = d0; g_r1[b] = r1; }
}

// ---------------------------------------------------------------------------
// pass 1: histogram bits[20:10] among values whose bits[31:21] == d0.
// Sparse updates (~10% match, spread over 2048 bins) -> 2 replicas enough.
// ---------------------------------------------------------------------------
__global__ void __launch_bounds__(256) hist1_kernel(const float4* __restrict__ coeffs) {
    __shared__ unsigned sh[2][2048];
    const int tid  = threadIdx.x;
    const int warp = tid >> 5;

    for (int i = tid; i < 2 * 2048; i += 256) ((unsigned*)sh)[i] = 0;
    __syncthreads();

    const int batch = blockIdx.y;
    const unsigned pref = g_d0[batch];
    unsigned* h = sh[warp & 1];
    const int base = blockIdx.x * PER_BLK;
    const float4* cb = coeffs + (size_t)batch * VEC_PB;

    for (int i = tid; i < PER_BLK; i += 512) {
        unsigned bb[8];
        LOAD8(bb, cb, base, i);
        #pragma unroll
        for (int j = 0; j < 8; j++) {
            unsigned b = bb[j];
            if ((b >> 21) == pref) atomicAdd(&h[(b >> 10) & 2047], 1u);
        }
    }
    __syncthreads();

    for (int i = tid; i < 2048; i += 256) {
        unsigned s = sh[0][i] + sh[1][i];
        if (s) atomicAdd(&g_hist[1][batch][i], s);
    }
}

// select pass 1: threshold = midpoint of resolved 1024-ulp bin
// (threshold rel err <= 2^-14 -> mask rel err ~3e-5; measured rel_err 3.2e-6)
__global__ void select1_kernel() {
    const int b = threadIdx.x >> 5;
    if (b >= BATCH) return;
    unsigned r2;
    unsigned d1 = warp_select<64>(g_hist[1][b], g_r1[b], &r2);
    if ((threadIdx.x & 31) == 0)
        g_thr[b] = __uint_as_float((g_d0[b] << 21) | (d1 << 10) | 512u);
}

// ---------------------------------------------------------------------------
// final: out[0..V)=coeffs*mask, out[V..2V)=mask, out[2V..3V)=importance.
// Streaming stores keep coeffs (read side) resident in L2.
// ---------------------------------------------------------------------------
__global__ void __launch_bounds__(256) final_kernel(const float4* __restrict__ coeffs,
                                                    const float* __restrict__ temp,
                                                    float4* __restrict__ out) {
    int ve = blockIdx.x * blockDim.x + threadIdx.x;   // 0 .. TOTALV-1
    int batch = ve >> 19;                             // VEC_PB = 2^19
    int vein = ve & (VEC_PB - 1);
    int eb = vein << 2;
    int t = eb >> 10;
    int d = eb & (HID - 1);
    int band = band_of(t);

    float4 imp = *reinterpret_cast<const float4*>(&g_imp5[band * HID + d]);
    float4 c = __ldg(&coeffs[ve]);
    float thr = g_thr[batch];
    float inv_t = __frcp_rn(fabsf(__ldg(&temp[0])));

    float4 mk, fl;
    { float ci = imp.x * fabsf(c.x); mk.x = sigmoidf_fast((ci - thr) * inv_t); fl.x = c.x * mk.x; }
    { float ci = imp.y * fabsf(c.y); mk.y = sigmoidf_fast((ci - thr) * inv_t); fl.y = c.y * mk.y; }
    { float ci = imp.z * fabsf(c.z); mk.z = sigmoidf_fast((ci - thr) * inv_t); fl.z = c.z * mk.z; }
    { float ci = imp.w * fabsf(c.w); mk.w = sigmoidf_fast((ci - thr) * inv_t); fl.w = c.w * mk.w; }

    __stcs(&out[ve], fl);
    __stcs(&out[TOTALV + ve], mk);
    __stcs(&out[2 * TOTALV + ve], imp);
}

// ---------------------------------------------------------------------------
// launch
// ---------------------------------------------------------------------------
extern "C" void kernel_launch(void* const* d_in, const int* in_sizes, int n_in,
                              void* d_out, int out_size) {
    const float* coeffs = (const float*)d_in[0];
    const float* bi     = (const float*)d_in[1];
    const float* di     = (const float*)d_in[2];
    const float* temp   = (const float*)d_in[3];
    float* out = (float*)d_out;

    setup_kernel<<<(2 * BATCH * 2048 + 255) / 256, 256>>>(bi, di);

    dim3 g(HBLK, BATCH);
    hist0_kernel<<<g, 256>>>((const float4*)coeffs);
    select0_kernel<<<1, 256>>>();
    hist1_kernel<<<g, 256>>>((const float4*)coeffs);
    select1_kernel<<<1, 256>>>();

    final_kernel<<<TOTALV / 256, 256>>>((const float4*)coeffs, temp, (float4*)out);
}

// round 7
// speedup vs baseline: 2.0142x; 1.0457x over previous
#include <cuda_runtime.h>
#include <math.h>
#include <stdint.h>

// Problem constants
#define BATCH   8
#define SEQ     2048
#define HID     1024
#define NPB     (SEQ * HID)        // 2,097,152 elements per batch
#define VEC_PB  (NPB / 4)          // 524,288 float4 per batch
#define TOTALV  (BATCH * VEC_PB)   // 4,194,304 float4 total
#define RANK0   1048576u           // 0-indexed ascending rank of threshold (N - k)
#define HBLK    128                // blocks per batch (16 rows each)
#define ROWS_PB 16                 // rows per block; band is constant per block

// Static scratch (no runtime allocation allowed)
__device__ __align__(16) float    g_imp5[5 * HID];       // sigmoid(band)*sigmoid(dim)
__device__ unsigned               g_hist[2][BATCH][2048];
__device__ unsigned               g_d0[BATCH];           // selected digit, pass 0
__device__ unsigned               g_r1[BATCH];           // remaining rank after pass 0
__device__ float                  g_thr[BATCH];

__device__ __forceinline__ float sigmoidf_fast(float x) {
    return 1.0f / (1.0f + __expf(-x));
}

// band(t): 0 for t<128, else floor(log2(t>>7)) + 1   (T=2048, L=4)
__device__ __forceinline__ int band_of(int t) {
    return (t >= 128) ? (32 - __clz(t >> 7)) : 0;
}

// ---------------------------------------------------------------------------
// setup: zero histograms, build importance table
// ---------------------------------------------------------------------------
__global__ void setup_kernel(const float* __restrict__ bi, const float* __restrict__ di) {
    int i = blockIdx.x * blockDim.x + threadIdx.x;
    if (i < 2 * BATCH * 2048) ((unsigned*)g_hist)[i] = 0;
    if (i < 5 * HID) {
        float sb = sigmoidf_fast(bi[i]);
        float sd = sigmoidf_fast(di[i & (HID - 1)]);
        g_imp5[i] = sb * sd;
    }
}

// ---------------------------------------------------------------------------
// pass 0: histogram bits[31:21]. grid (HBLK, BATCH) x 256.
// Block = 16 contiguous rows (single band); thread = one float4 column.
// imp4 is a per-thread constant. 4-replica smem hist, plain atomics.
// ---------------------------------------------------------------------------
__global__ void __launch_bounds__(256) hist0_kernel(const float4* __restrict__ coeffs) {
    __shared__ unsigned sh[4][2048];
    const int tid = threadIdx.x;

    for (int i = tid; i < 4 * 2048; i += 256) ((unsigned*)sh)[i] = 0;
    __syncthreads();

    const int batch = blockIdx.y;
    unsigned* h = sh[(tid >> 5) & 3];
    const int band = band_of(blockIdx.x << 4);
    const float4 imp = *reinterpret_cast<const float4*>(&g_imp5[band * HID + (tid << 2)]);
    const float4* p = coeffs + (size_t)batch * VEC_PB + (size_t)blockIdx.x * (ROWS_PB * 256) + tid;

    #pragma unroll
    for (int r = 0; r < ROWS_PB; r += 4) {
        float4 c0 = __ldg(p + (r + 0) * 256);
        float4 c1 = __ldg(p + (r + 1) * 256);
        float4 c2 = __ldg(p + (r + 2) * 256);
        float4 c3 = __ldg(p + (r + 3) * 256);
        atomicAdd(&h[__float_as_uint(imp.x * fabsf(c0.x)) >> 21], 1u);
        atomicAdd(&h[__float_as_uint(imp.y * fabsf(c0.y)) >> 21], 1u);
        atomicAdd(&h[__float_as_uint(imp.z * fabsf(c0.z)) >> 21], 1u);
        atomicAdd(&h[__float_as_uint(imp.w * fabsf(c0.w)) >> 21], 1u);
        atomicAdd(&h[__float_as_uint(imp.x * fabsf(c1.x)) >> 21], 1u);
        atomicAdd(&h[__float_as_uint(imp.y * fabsf(c1.y)) >> 21], 1u);
        atomicAdd(&h[__float_as_uint(imp.z * fabsf(c1.z)) >> 21], 1u);
        atomicAdd(&h[__float_as_uint(imp.w * fabsf(c1.w)) >> 21], 1u);
        atomicAdd(&h[__float_as_uint(imp.x * fabsf(c2.x)) >> 21], 1u);
        atomicAdd(&h[__float_as_uint(imp.y * fabsf(c2.y)) >> 21], 1u);
        atomicAdd(&h[__float_as_uint(imp.z * fabsf(c2.z)) >> 21], 1u);
        atomicAdd(&h[__float_as_uint(imp.w * fabsf(c2.w)) >> 21], 1u);
        atomicAdd(&h[__float_as_uint(imp.x * fabsf(c3.x)) >> 21], 1u);
        atomicAdd(&h[__float_as_uint(imp.y * fabsf(c3.y)) >> 21], 1u);
        atomicAdd(&h[__float_as_uint(imp.z * fabsf(c3.z)) >> 21], 1u);
        atomicAdd(&h[__float_as_uint(imp.w * fabsf(c3.w)) >> 21], 1u);
    }
    __syncthreads();

    for (int i = tid; i < 2048; i += 256) {
        unsigned s = sh[0][i] + sh[1][i] + sh[2][i] + sh[3][i];
        if (s) atomicAdd(&g_hist[0][batch][i], s);
    }
}

// ---------------------------------------------------------------------------
// warp-collective digit select over a 32*PER-bin histogram.
// ---------------------------------------------------------------------------
template <int PER>
__device__ __forceinline__ unsigned warp_select(const unsigned* __restrict__ h,
                                                unsigned rank, unsigned* rem) {
    const int lane = threadIdx.x & 31;
    unsigned s = 0;
    #pragma unroll
    for (int j = 0; j < PER; j++) s += h[lane * PER + j];

    unsigned v = s;
    #pragma unroll
    for (int o = 1; o < 32; o <<= 1) {
        unsigned t = __shfl_up_sync(0xFFFFFFFFu, v, o);
        if (lane >= o) v += t;
    }
    unsigned excl = v - s;

    bool in = (rank >= excl) && (rank < excl + s);
    unsigned m = __ballot_sync(0xFFFFFFFFu, in);
    int L = __ffs(m) - 1;

    unsigned dig = 0, r2 = 0;
    if (lane == L) {
        unsigned cum = excl;
        #pragma unroll 1
        for (int j = 0; j < PER; j++) {
            unsigned c = h[lane * PER + j];
            if (rank < cum + c) { dig = (unsigned)(lane * PER + j); r2 = rank - cum; break; }
            cum += c;
        }
    }
    dig = __shfl_sync(0xFFFFFFFFu, dig, L);
    r2  = __shfl_sync(0xFFFFFFFFu, r2,  L);
    *rem = r2;
    return dig;
}

// select pass 0: one block, warp w handles batch w
__global__ void select0_kernel() {
    const int b = threadIdx.x >> 5;
    if (b >= BATCH) return;
    unsigned r1;
    unsigned d0 = warp_select<64>(g_hist[0][b], RANK0, &r1);
    if ((threadIdx.x & 31) == 0) { g_d0[b] = d0; g_r1[b] = r1; }
}

// ---------------------------------------------------------------------------
// pass 1: histogram bits[20:10] among values with bits[31:21] == d0.
// Same tiling; sparse updates -> 2 replicas.
// ---------------------------------------------------------------------------
__global__ void __launch_bounds__(256) hist1_kernel(const float4* __restrict__ coeffs) {
    __shared__ unsigned sh[2][2048];
    const int tid = threadIdx.x;

    for (int i = tid; i < 2 * 2048; i += 256) ((unsigned*)sh)[i] = 0;
    __syncthreads();

    const int batch = blockIdx.y;
    const unsigned pref = g_d0[batch];
    unsigned* h = sh[(tid >> 5) & 1];
    const int band = band_of(blockIdx.x << 4);
    const float4 imp = *reinterpret_cast<const float4*>(&g_imp5[band * HID + (tid << 2)]);
    const float4* p = coeffs + (size_t)batch * VEC_PB + (size_t)blockIdx.x * (ROWS_PB * 256) + tid;

    #pragma unroll
    for (int r = 0; r < ROWS_PB; r += 4) {
        float4 c0 = __ldg(p + (r + 0) * 256);
        float4 c1 = __ldg(p + (r + 1) * 256);
        float4 c2 = __ldg(p + (r + 2) * 256);
        float4 c3 = __ldg(p + (r + 3) * 256);
        unsigned bb[16];
        bb[0]  = __float_as_uint(imp.x * fabsf(c0.x));
        bb[1]  = __float_as_uint(imp.y * fabsf(c0.y));
        bb[2]  = __float_as_uint(imp.z * fabsf(c0.z));
        bb[3]  = __float_as_uint(imp.w * fabsf(c0.w));
        bb[4]  = __float_as_uint(imp.x * fabsf(c1.x));
        bb[5]  = __float_as_uint(imp.y * fabsf(c1.y));
        bb[6]  = __float_as_uint(imp.z * fabsf(c1.z));
        bb[7]  = __float_as_uint(imp.w * fabsf(c1.w));
        bb[8]  = __float_as_uint(imp.x * fabsf(c2.x));
        bb[9]  = __float_as_uint(imp.y * fabsf(c2.y));
        bb[10] = __float_as_uint(imp.z * fabsf(c2.z));
        bb[11] = __float_as_uint(imp.w * fabsf(c2.w));
        bb[12] = __float_as_uint(imp.x * fabsf(c3.x));
        bb[13] = __float_as_uint(imp.y * fabsf(c3.y));
        bb[14] = __float_as_uint(imp.z * fabsf(c3.z));
        bb[15] = __float_as_uint(imp.w * fabsf(c3.w));
        #pragma unroll
        for (int j = 0; j < 16; j++)
            if ((bb[j] >> 21) == pref) atomicAdd(&h[(bb[j] >> 10) & 2047], 1u);
    }
    __syncthreads();

    for (int i = tid; i < 2048; i += 256) {
        unsigned s = sh[0][i] + sh[1][i];
        if (s) atomicAdd(&g_hist[1][batch][i], s);
    }
}

// select pass 1: threshold = midpoint of resolved 1024-ulp bin
// (threshold rel err <= 2^-14; measured end-to-end rel_err 3.2e-6)
__global__ void select1_kernel() {
    const int b = threadIdx.x >> 5;
    if (b >= BATCH) return;
    unsigned r2;
    unsigned d1 = warp_select<64>(g_hist[1][b], g_r1[b], &r2);
    if ((threadIdx.x & 31) == 0)
        g_thr[b] = __uint_as_float((g_d0[b] << 21) | (d1 << 10) | 512u);
}

// ---------------------------------------------------------------------------
// final: out[0..V)=coeffs*mask, out[V..2V)=mask, out[2V..3V)=importance.
// Same tiling: imp4 per-thread constant; importance written from registers.
// Streaming stores keep coeffs resident in L2 for the next replay.
// ---------------------------------------------------------------------------
__global__ void __launch_bounds__(256) final_kernel(const float4* __restrict__ coeffs,
                                                    const float* __restrict__ temp,
                                                    float4* __restrict__ out) {
    const int tid = threadIdx.x;
    const int batch = blockIdx.y;
    const int band = band_of(blockIdx.x << 4);
    const float4 imp = *reinterpret_cast<const float4*>(&g_imp5[band * HID + (tid << 2)]);
    const float thr = g_thr[batch];
    const float inv_t = __frcp_rn(fabsf(__ldg(&temp[0])));

    const size_t vbase = (size_t)batch * VEC_PB + (size_t)blockIdx.x * (ROWS_PB * 256) + tid;
    const float4* p = coeffs + vbase;

    #pragma unroll
    for (int r = 0; r < ROWS_PB; r += 2) {
        float4 c0 = __ldg(p + (r + 0) * 256);
        float4 c1 = __ldg(p + (r + 1) * 256);

        float4 mk0, fl0, mk1, fl1;
        { float ci = imp.x * fabsf(c0.x); mk0.x = sigmoidf_fast((ci - thr) * inv_t); fl0.x = c0.x * mk0.x; }
        { float ci = imp.y * fabsf(c0.y); mk0.y = sigmoidf_fast((ci - thr) * inv_t); fl0.y = c0.y * mk0.y; }
        { float ci = imp.z * fabsf(c0.z); mk0.z = sigmoidf_fast((ci - thr) * inv_t); fl0.z = c0.z * mk0.z; }
        { float ci = imp.w * fabsf(c0.w); mk0.w = sigmoidf_fast((ci - thr) * inv_t); fl0.w = c0.w * mk0.w; }
        { float ci = imp.x * fabsf(c1.x); mk1.x = sigmoidf_fast((ci - thr) * inv_t); fl1.x = c1.x * mk1.x; }
        { float ci = imp.y * fabsf(c1.y); mk1.y = sigmoidf_fast((ci - thr) * inv_t); fl1.y = c1.y * mk1.y; }
        { float ci = imp.z * fabsf(c1.z); mk1.z = sigmoidf_fast((ci - thr) * inv_t); fl1.z = c1.z * mk1.z; }
        { float ci = imp.w * fabsf(c1.w); mk1.w = sigmoidf_fast((ci - thr) * inv_t); fl1.w = c1.w * mk1.w; }

        size_t ve0 = vbase + (size_t)(r + 0) * 256;
        size_t ve1 = vbase + (size_t)(r + 1) * 256;
        __stcs(&out[ve0], fl0);
        __stcs(&out[ve1], fl1);
        __stcs(&out[TOTALV + ve0], mk0);
        __stcs(&out[TOTALV + ve1], mk1);
        __stcs(&out[2 * TOTALV + ve0], imp);
        __stcs(&out[2 * TOTALV + ve1], imp);
    }
}

// ---------------------------------------------------------------------------
// launch
// ---------------------------------------------------------------------------
extern "C" void kernel_launch(void* const* d_in, const int* in_sizes, int n_in,
                              void* d_out, int out_size) {
    const float* coeffs = (const float*)d_in[0];
    const float* bi     = (const float*)d_in[1];
    const float* di     = (const float*)d_in[2];
    const float* temp   = (const float*)d_in[3];
    float* out = (float*)d_out;

    setup_kernel<<<(2 * BATCH * 2048 + 255) / 256, 256>>>(bi, di);

    dim3 g(HBLK, BATCH);
    hist0_kernel<<<g, 256>>>((const float4*)coeffs);
    select0_kernel<<<1, 256>>>();
    hist1_kernel<<<g, 256>>>((const float4*)coeffs);
    select1_kernel<<<1, 256>>>();

    final_kernel<<<g, 256>>>((const float4*)coeffs, temp, (float4*)out);
}